// round 15
// baseline (speedup 1.0000x reference)
#include <cuda_runtime.h>
#include <cuda_bf16.h>
#include <cstdint>

// ---------------- problem constants ----------------
constexpr int Bc = 4, Tc = 4096, Cc = 120, Hc = 64;
constexpr float SCALE = 0.09128709291752768f;  // 1/sqrt(C)
constexpr int KTILE = 64;
constexpr int HKT = 32;           // key tiles per half (Tc/KTILE/2)
constexpr int RSTRIDE = 288;      // smem row stride bytes (72 words; 72%32=8 -> LDS.64 conflict-free)
constexpr int VOFF = 64 * RSTRIDE;        // V region offset in stage
constexpr int STAGE = 2 * 64 * RSTRIDE;   // 36864 bytes per stage (K + V)

// ---------------- device scratch (allocation-free rule) ----------------
__device__ __align__(16) float g_q[Bc * Tc * Hc];   // tf32-rounded, SCALE folded
__device__ __align__(16) float g_k[Bc * Tc * Hc];   // tf32-rounded
__device__ __align__(16) float g_vt[Bc * Hc * Tc];  // tf32-rounded, [b][h][t]
__device__ __align__(16) float g_acc[2][Bc * Tc * Hc];  // partial O per key-half
__device__ __align__(16) float g_rs[2][Bc * Tc];        // partial rowsums

// ---------------- PTX helpers (sm_80+ baseline) ----------------
__device__ __forceinline__ void mma_tf32(float* d, const uint32_t* a,
                                         uint32_t b0, uint32_t b1) {
    asm volatile(
        "mma.sync.aligned.m16n8k8.row.col.f32.tf32.tf32.f32 "
        "{%0,%1,%2,%3}, {%4,%5,%6,%7}, {%8,%9}, {%0,%1,%2,%3};"
        : "+f"(d[0]), "+f"(d[1]), "+f"(d[2]), "+f"(d[3])
        : "r"(a[0]), "r"(a[1]), "r"(a[2]), "r"(a[3]), "r"(b0), "r"(b1));
}
__device__ __forceinline__ void lds64(uint32_t& r0, uint32_t& r1, uint32_t a) {
    asm volatile("ld.shared.v2.b32 {%0,%1}, [%2];" : "=r"(r0), "=r"(r1) : "r"(a));
}
__device__ __forceinline__ uint32_t smem_u32(const void* p) {
    uint32_t a;
    asm("{ .reg .u64 t; cvta.to.shared.u64 t, %1; cvt.u32.u64 %0, t; }"
        : "=r"(a) : "l"(p));
    return a;
}
__device__ __forceinline__ void cpasync16(uint32_t dst, const void* src) {
    asm volatile("cp.async.ca.shared.global [%0], [%1], 16;" :: "r"(dst), "l"(src));
}
#define CP_COMMIT() asm volatile("cp.async.commit_group;" ::: "memory")
#define CP_WAIT0()  asm volatile("cp.async.wait_group 0;" ::: "memory")

__device__ __forceinline__ float to_tf32(float x) {
    float r;
    asm("cvt.rna.tf32.f32 %0, %1;" : "=f"(r) : "f"(x));
    return r;
}
__device__ __forceinline__ uint32_t tf32_bits(uint32_t u) {
    float r;
    asm("cvt.rna.tf32.f32 %0, %1;" : "=f"(r) : "f"(__uint_as_float(u)));
    return __float_as_uint(r);
}

// ---------------- Kernel 1: tf32 MMA QKV projection ----------------
// 128 CTAs x 256 thr (one wave), 128 rows/CTA. x staged RAW via cp.async
// (issued first; W staging overlaps the flight); tf32 rounding of x happens
// in registers at A-fragment load.
constexpr int PSTR = 136;  // smem row stride in words (136 % 32 == 8)
constexpr int PROJ_SMEM = (192 * PSTR + 128 * PSTR) * 4;  // 174,080 B
__global__ void __launch_bounds__(256, 1)
proj_kernel(const float* __restrict__ x,
            const float* __restrict__ Wk,
            const float* __restrict__ Wq,
            const float* __restrict__ Wv) {
    extern __shared__ float ps[];
    float* sW = ps;                // [192][PSTR]  rows: 0-63 K, 64-127 Q, 128-191 V
    float* sx = ps + 192 * PSTR;   // [128][PSTR]  raw fp32 x

    const int tid = threadIdx.x;
    const int row0 = blockIdx.x * 128;

    // ---- x tile via cp.async FIRST (raw, no rounding) ----
    {
        const uint32_t sxa = smem_u32(sx);
        const float4* xg = reinterpret_cast<const float4*>(x + (long long)row0 * Cc);
#pragma unroll
        for (int it = 0; it < 15; it++) {
            const int i = tid + it * 256;  // 0..3839 float4 chunks
            const int r = i / 30, c4 = i % 30;
            cpasync16(sxa + (uint32_t)((r * PSTR + c4 * 4) * 4), xg + i);
        }
        CP_COMMIT();
    }

    // ---- W transposed into smem (tf32-rounded) while x is in flight ----
    {
        const float* Ws[3] = {Wk, Wq, Wv};
#pragma unroll
        for (int m = 0; m < 3; m++) {
            const float* W = Ws[m];
            for (int i = tid; i < Cc * Hc; i += 256) {
                const int c = i >> 6, h = i & 63;
                sW[(m * 64 + h) * PSTR + c] = to_tf32(W[i]);
            }
        }
    }

    CP_WAIT0();
    __syncthreads();

    const int w = tid >> 5, lane = tid & 31;
    const int g = lane >> 2, tig = lane & 3;
    const int m0 = w * 16;

    float acc[24][4];
#pragma unroll
    for (int nt = 0; nt < 24; nt++)
#pragma unroll
        for (int i = 0; i < 4; i++) acc[nt][i] = 0.f;

    const uint32_t aA0 = smem_u32(sx) + (uint32_t)(((m0 + g) * PSTR + 2 * tig) * 4);
    const uint32_t aA1 = aA0 + (uint32_t)(8 * PSTR * 4);
    const uint32_t aB  = smem_u32(sW) + (uint32_t)((g * PSTR + 2 * tig) * 4);

#pragma unroll
    for (int s = 0; s < 15; s++) {
        uint32_t a0, a1, a2, a3;
        lds64(a0, a2, aA0 + (uint32_t)s * 32);   // rows m0+g:   cols 8s+2tig, +1
        lds64(a1, a3, aA1 + (uint32_t)s * 32);   // rows m0+g+8
        uint32_t af[4] = {tf32_bits(a0), tf32_bits(a1), tf32_bits(a2), tf32_bits(a3)};
#pragma unroll
        for (int nt = 0; nt < 24; nt++) {
            uint32_t b0, b1;
            lds64(b0, b1, aB + (uint32_t)(nt * 8 * PSTR) * 4 + (uint32_t)s * 32);
            mma_tf32(acc[nt], af, b0, b1);
        }
    }

    // ---- epilogue: tf32-round and store K / Q(scaled) / V(transposed) ----
    const int t0 = row0 + m0 + g;
#pragma unroll
    for (int nt = 0; nt < 8; nt++) {  // K: n 0..63
        const int h = nt * 8 + 2 * tig;
        *(float2*)&g_k[(long long)t0 * Hc + h] =
            make_float2(to_tf32(acc[nt][0]), to_tf32(acc[nt][1]));
        *(float2*)&g_k[(long long)(t0 + 8) * Hc + h] =
            make_float2(to_tf32(acc[nt][2]), to_tf32(acc[nt][3]));
    }
#pragma unroll
    for (int nt = 8; nt < 16; nt++) {  // Q: n 64..127 (scale folded)
        const int h = (nt - 8) * 8 + 2 * tig;
        *(float2*)&g_q[(long long)t0 * Hc + h] =
            make_float2(to_tf32(acc[nt][0] * SCALE), to_tf32(acc[nt][1] * SCALE));
        *(float2*)&g_q[(long long)(t0 + 8) * Hc + h] =
            make_float2(to_tf32(acc[nt][2] * SCALE), to_tf32(acc[nt][3] * SCALE));
    }
    {
        const int b = row0 >> 12, tl = t0 & 4095;
#pragma unroll
        for (int nt = 16; nt < 24; nt++) {  // V: n 128..191, transposed [h][t]
            const int h = (nt - 16) * 8 + 2 * tig;
            float* v0 = g_vt + ((long long)(b * Hc + h)) * Tc + tl;
            float* v1 = g_vt + ((long long)(b * Hc + h + 1)) * Tc + tl;
            v0[0] = to_tf32(acc[nt][0]);
            v1[0] = to_tf32(acc[nt][1]);
            v0[8] = to_tf32(acc[nt][2]);
            v1[8] = to_tf32(acc[nt][3]);
        }
    }
}

// ---------------- Kernel 2: tf32 flash attention, 32 q/warp, key-split ----------------
// Relabeled fragments (QK C-frag == PV A-frag; B pairs adjacent -> lds64) +
// 2-DEEP QK lookahead: QK(j+2) issues between exp(j)'s MUFUs and PV(j), so
// the tensor pipe holds a 16-MMA backlog across the exp->cvt->pack window.
__global__ void __launch_bounds__(256, 1)
attn_kernel() {
    extern __shared__ char dsm[];  // 2 x STAGE

    const int tid = threadIdx.x;
    const int w = tid >> 5;
    const int lane = tid & 31;
    const int g = lane >> 2;
    const int tig = lane & 3;
    const int b = blockIdx.y;
    const int half = blockIdx.z;
    const int qbase = blockIdx.x * 256 + w * 32;
    const long long qrow = (long long)b * Tc + qbase + g;

    // ---- Q fragments: dims {8s+2tig, 8s+2tig+1} in slots {tig, tig+4} ----
    uint32_t qf0[8][4], qf1[8][4];
#pragma unroll
    for (int s = 0; s < 8; s++) {
        const float2 a0 = *(const float2*)&g_q[qrow * Hc + 8 * s + 2 * tig];
        const float2 a1 = *(const float2*)&g_q[(qrow + 8) * Hc + 8 * s + 2 * tig];
        const float2 a2 = *(const float2*)&g_q[(qrow + 16) * Hc + 8 * s + 2 * tig];
        const float2 a3 = *(const float2*)&g_q[(qrow + 24) * Hc + 8 * s + 2 * tig];
        qf0[s][0] = __float_as_uint(a0.x);
        qf0[s][1] = __float_as_uint(a1.x);
        qf0[s][2] = __float_as_uint(a0.y);
        qf0[s][3] = __float_as_uint(a1.y);
        qf1[s][0] = __float_as_uint(a2.x);
        qf1[s][1] = __float_as_uint(a3.x);
        qf1[s][2] = __float_as_uint(a2.y);
        qf1[s][3] = __float_as_uint(a3.y);
    }

    float O0[8][4], O1[8][4];
#pragma unroll
    for (int j = 0; j < 8; j++)
#pragma unroll
        for (int i = 0; i < 4; i++) { O0[j][i] = 0.f; O1[j][i] = 0.f; }
    float rl0 = 0.f, rh0 = 0.f, rl1 = 0.f, rh1 = 0.f;

    const uint32_t sb = smem_u32(dsm);
    const uint32_t fragoff = (uint32_t)(g * RSTRIDE + tig * 8);

    auto prefetch = [&](int kt, int p) {
        const uint32_t bb = sb + p * STAGE;
        const int ktg = half * HKT + kt;
        const long long kb = (long long)b * Tc + ktg * KTILE;
        const float* vbase = g_vt + (long long)b * Hc * Tc + ktg * KTILE;
#pragma unroll
        for (int it = 0; it < 4; it++) {
            const int c = tid + it * 256;  // 0..1023
            const int row = c >> 4, col = c & 15;
            const uint32_t doff = (uint32_t)(row * RSTRIDE + col * 16);
            cpasync16(bb + doff, g_k + (kb + row) * Hc + col * 4);
            cpasync16(bb + VOFF + doff, vbase + (long long)row * Tc + col * 4);
        }
    };

    prefetch(0, 0);
    CP_COMMIT();

    float S[3][2][4];  // 3 rotating S buffers [slot][chunk][frag]

    for (int kt = 0; kt < HKT; kt++) {
        CP_WAIT0();
        __syncthreads();
        if (kt + 1 < HKT) {
            prefetch(kt + 1, (kt + 1) & 1);
            CP_COMMIT();
        }

        const uint32_t bb = sb + (kt & 1) * STAGE;
        const uint32_t aK = bb + fragoff;
        const uint32_t aV = bb + VOFF + fragoff;

        auto qk_ntile = [&](int j, int p) {
            float* S0 = S[p][0];
            float* S1 = S[p][1];
#pragma unroll
            for (int i = 0; i < 4; i++) { S0[i] = 0.f; S1[i] = 0.f; }
            const uint32_t base = aK + (uint32_t)j * (8 * RSTRIDE);
#pragma unroll
            for (int s = 0; s < 8; s++) {
                uint32_t b0, b1;
                lds64(b0, b1, base + s * 32);
                mma_tf32(S0, qf0[s], b0, b1);
                mma_tf32(S1, qf1[s], b0, b1);
            }
        };

        qk_ntile(0, 0);
        qk_ntile(1, 1);

#pragma unroll
        for (int j = 0; j < 8; j++) {
            const int sl = j % 3;
            const float* S0 = S[sl][0];
            const float* S1 = S[sl][1];

            // exp MUFUs first (only need S(j))
            const float e0 = __expf(S0[0]), e1 = __expf(S0[1]);
            const float e2 = __expf(S0[2]), e3 = __expf(S0[3]);
            const float f0 = __expf(S1[0]), f1 = __expf(S1[1]);
            const float f2 = __expf(S1[2]), f3 = __expf(S1[3]);

            // 2-deep lookahead: fresh 16-MMA block inside the exp window
            if (j < 6) qk_ntile(j + 2, (j + 2) % 3);

            rl0 += e0 + e1;
            rh0 += e2 + e3;
            rl1 += f0 + f1;
            rh1 += f2 + f3;
            uint32_t pf0[4], pf1[4];
            pf0[0] = __float_as_uint(to_tf32(e0));
            pf0[1] = __float_as_uint(to_tf32(e2));
            pf0[2] = __float_as_uint(to_tf32(e1));
            pf0[3] = __float_as_uint(to_tf32(e3));
            pf1[0] = __float_as_uint(to_tf32(f0));
            pf1[1] = __float_as_uint(to_tf32(f2));
            pf1[2] = __float_as_uint(to_tf32(f1));
            pf1[3] = __float_as_uint(to_tf32(f3));

            const uint32_t vbase = aV + (uint32_t)j * 32;
#pragma unroll
            for (int jd = 0; jd < 8; jd++) {
                uint32_t b0, b1;
                lds64(b0, b1, vbase + (uint32_t)jd * (8 * RSTRIDE));
                mma_tf32(O0[jd], pf0, b0, b1);
                mma_tf32(O1[jd], pf1, b0, b1);
            }
        }
    }

    // ---- reduce rowsums over tig; write partial O + rowsums ----
    rl0 += __shfl_xor_sync(0xffffffffu, rl0, 1);
    rl0 += __shfl_xor_sync(0xffffffffu, rl0, 2);
    rh0 += __shfl_xor_sync(0xffffffffu, rh0, 1);
    rh0 += __shfl_xor_sync(0xffffffffu, rh0, 2);
    rl1 += __shfl_xor_sync(0xffffffffu, rl1, 1);
    rl1 += __shfl_xor_sync(0xffffffffu, rl1, 2);
    rh1 += __shfl_xor_sync(0xffffffffu, rh1, 1);
    rh1 += __shfl_xor_sync(0xffffffffu, rh1, 2);

    float* acc = g_acc[half];
    if (tig == 0) {
        float* rs = g_rs[half] + (long long)b * Tc + qbase + g;
        rs[0] = rl0;
        rs[8] = rh0;
        rs[16] = rl1;
        rs[24] = rh1;
    }
#pragma unroll
    for (int j = 0; j < 8; j++) {
        const int d0 = 8 * j + 2 * tig;
        *(float2*)&acc[qrow * Hc + d0] = make_float2(O0[j][0], O0[j][1]);
        *(float2*)&acc[(qrow + 8) * Hc + d0] = make_float2(O0[j][2], O0[j][3]);
        *(float2*)&acc[(qrow + 16) * Hc + d0] = make_float2(O1[j][0], O1[j][1]);
        *(float2*)&acc[(qrow + 24) * Hc + d0] = make_float2(O1[j][2], O1[j][3]);
    }
}

// ---------------- Kernel 3: combine key-halves + normalize ----------------
__global__ void __launch_bounds__(256)
combine_kernel(float* __restrict__ out) {
    const int idx = blockIdx.x * 256 + threadIdx.x;  // 0 .. B*T*16-1
    const int row = idx >> 4;
    const float4 a = reinterpret_cast<const float4*>(g_acc[0])[idx];
    const float4 d = reinterpret_cast<const float4*>(g_acc[1])[idx];
    const float inv = 1.0f / (g_rs[0][row] + g_rs[1][row]);
    float4 o;
    o.x = (a.x + d.x) * inv;
    o.y = (a.y + d.y) * inv;
    o.z = (a.z + d.z) * inv;
    o.w = (a.w + d.w) * inv;
    reinterpret_cast<float4*>(out)[idx] = o;
}

extern "C" void kernel_launch(void* const* d_in, const int* in_sizes, int n_in,
                              void* d_out, int out_size) {
    // x is the unique large tensor; weights keep relative order Wk, Wq, Wv.
    const float* x = nullptr;
    const float* w[3] = {nullptr, nullptr, nullptr};
    int wn = 0;
    for (int i = 0; i < n_in; i++) {
        if (in_sizes[i] == Bc * Tc * Cc) x = (const float*)d_in[i];
        else if (wn < 3) w[wn++] = (const float*)d_in[i];
    }

    static bool configured = false;
    if (!configured) {
        cudaFuncSetAttribute(proj_kernel, cudaFuncAttributeMaxDynamicSharedMemorySize,
                             PROJ_SMEM);
        cudaFuncSetAttribute(attn_kernel, cudaFuncAttributeMaxDynamicSharedMemorySize,
                             2 * STAGE);
        configured = true;
    }

    proj_kernel<<<128, 256, PROJ_SMEM>>>(x, w[0], w[1], w[2]);

    dim3 grid(Tc / 256, Bc, 2);
    attn_kernel<<<grid, 256, 2 * STAGE>>>();

    combine_kernel<<<Bc * Tc * 16 / 256, 256>>>((float*)d_out);
}

// round 16
// speedup vs baseline: 1.6300x; 1.6300x over previous
#include <cuda_runtime.h>
#include <cuda_fp16.h>
#include <cstdint>

// ---------------- problem constants ----------------
constexpr int Bc = 4, Tc = 4096, Cc = 120, Hc = 64;
constexpr float SCALE = 0.09128709291752768f;  // 1/sqrt(C)
constexpr int KTILE = 64;
constexpr int HKT = 32;            // key tiles per half (Tc/KTILE/2)
constexpr int KSTR = 144;          // smem row stride bytes (72 halves; R5-verified for ldmatrix)
constexpr int VOFF = 64 * KSTR;    // V region offset in stage (9216)
constexpr int STAGE = 2 * 64 * KSTR;  // 18432 bytes per stage (K + V)

// ---------------- device scratch (allocation-free rule) ----------------
__device__ __align__(16) __half g_q[Bc * Tc * Hc];   // fp16, SCALE folded
__device__ __align__(16) __half g_k[Bc * Tc * Hc];   // fp16
__device__ __align__(16) __half g_vt[Bc * Hc * Tc];  // fp16, [b][h][t]
__device__ __align__(16) float g_acc[2][Bc * Tc * Hc];  // partial O per key-half
__device__ __align__(16) float g_rs[2][Bc * Tc];        // partial rowsums

// ---------------- PTX helpers (sm_80+ baseline) ----------------
__device__ __forceinline__ void mma_f16(float* d, const uint32_t* a,
                                        uint32_t b0, uint32_t b1) {
    asm volatile(
        "mma.sync.aligned.m16n8k16.row.col.f32.f16.f16.f32 "
        "{%0,%1,%2,%3}, {%4,%5,%6,%7}, {%8,%9}, {%0,%1,%2,%3};"
        : "+f"(d[0]), "+f"(d[1]), "+f"(d[2]), "+f"(d[3])
        : "r"(a[0]), "r"(a[1]), "r"(a[2]), "r"(a[3]), "r"(b0), "r"(b1));
}
__device__ __forceinline__ void mma_tf32(float* d, const uint32_t* a,
                                         uint32_t b0, uint32_t b1) {
    asm volatile(
        "mma.sync.aligned.m16n8k8.row.col.f32.tf32.tf32.f32 "
        "{%0,%1,%2,%3}, {%4,%5,%6,%7}, {%8,%9}, {%0,%1,%2,%3};"
        : "+f"(d[0]), "+f"(d[1]), "+f"(d[2]), "+f"(d[3])
        : "r"(a[0]), "r"(a[1]), "r"(a[2]), "r"(a[3]), "r"(b0), "r"(b1));
}
__device__ __forceinline__ void ldsm2(uint32_t& r0, uint32_t& r1, uint32_t addr) {
    asm volatile("ldmatrix.sync.aligned.m8n8.x2.shared.b16 {%0,%1}, [%2];"
                 : "=r"(r0), "=r"(r1) : "r"(addr));
}
__device__ __forceinline__ void lds64(uint32_t& r0, uint32_t& r1, uint32_t a) {
    asm volatile("ld.shared.v2.b32 {%0,%1}, [%2];" : "=r"(r0), "=r"(r1) : "r"(a));
}
__device__ __forceinline__ uint32_t smem_u32(const void* p) {
    uint32_t a;
    asm("{ .reg .u64 t; cvta.to.shared.u64 t, %1; cvt.u32.u64 %0, t; }"
        : "=r"(a) : "l"(p));
    return a;
}
__device__ __forceinline__ void cpasync16(uint32_t dst, const void* src) {
    asm volatile("cp.async.ca.shared.global [%0], [%1], 16;" :: "r"(dst), "l"(src));
}
#define CP_COMMIT() asm volatile("cp.async.commit_group;" ::: "memory")
#define CP_WAIT0()  asm volatile("cp.async.wait_group 0;" ::: "memory")

__device__ __forceinline__ float to_tf32(float x) {
    float r;
    asm("cvt.rna.tf32.f32 %0, %1;" : "=f"(r) : "f"(x));
    return r;
}
__device__ __forceinline__ uint32_t tf32_bits(uint32_t u) {
    float r;
    asm("cvt.rna.tf32.f32 %0, %1;" : "=f"(r) : "f"(__uint_as_float(u)));
    return __float_as_uint(r);
}
// pack two f32 into f16x2: low half = lo, high half = hi (R5-verified convention)
__device__ __forceinline__ uint32_t pkh(float hi, float lo) {
    uint32_t r;
    asm("cvt.rn.f16x2.f32 %0, %1, %2;" : "=r"(r) : "f"(hi), "f"(lo));
    return r;
}

// ---------------- Kernel 1: tf32 MMA QKV projection, fp16 outputs ----------------
constexpr int PSTR = 136;  // smem row stride in words (136 % 32 == 8)
constexpr int PROJ_SMEM = (192 * PSTR + 128 * PSTR) * 4;  // 174,080 B
__global__ void __launch_bounds__(256, 1)
proj_kernel(const float* __restrict__ x,
            const float* __restrict__ Wk,
            const float* __restrict__ Wq,
            const float* __restrict__ Wv) {
    extern __shared__ float ps[];
    float* sW = ps;                // [192][PSTR]  rows: 0-63 K, 64-127 Q, 128-191 V
    float* sx = ps + 192 * PSTR;   // [128][PSTR]  raw fp32 x

    const int tid = threadIdx.x;
    const int row0 = blockIdx.x * 128;

    // ---- x tile via cp.async FIRST (raw) ----
    {
        const uint32_t sxa = smem_u32(sx);
        const float4* xg = reinterpret_cast<const float4*>(x + (long long)row0 * Cc);
#pragma unroll
        for (int it = 0; it < 15; it++) {
            const int i = tid + it * 256;
            const int r = i / 30, c4 = i % 30;
            cpasync16(sxa + (uint32_t)((r * PSTR + c4 * 4) * 4), xg + i);
        }
        CP_COMMIT();
    }
    // ---- W transposed into smem (tf32-rounded) while x is in flight ----
    {
        const float* Ws[3] = {Wk, Wq, Wv};
#pragma unroll
        for (int m = 0; m < 3; m++) {
            const float* W = Ws[m];
            for (int i = tid; i < Cc * Hc; i += 256) {
                const int c = i >> 6, h = i & 63;
                sW[(m * 64 + h) * PSTR + c] = to_tf32(W[i]);
            }
        }
    }
    CP_WAIT0();
    __syncthreads();

    const int w = tid >> 5, lane = tid & 31;
    const int g = lane >> 2, tig = lane & 3;
    const int m0 = w * 16;

    float acc[24][4];
#pragma unroll
    for (int nt = 0; nt < 24; nt++)
#pragma unroll
        for (int i = 0; i < 4; i++) acc[nt][i] = 0.f;

    const uint32_t aA0 = smem_u32(sx) + (uint32_t)(((m0 + g) * PSTR + 2 * tig) * 4);
    const uint32_t aA1 = aA0 + (uint32_t)(8 * PSTR * 4);
    const uint32_t aB  = smem_u32(sW) + (uint32_t)((g * PSTR + 2 * tig) * 4);

#pragma unroll
    for (int s = 0; s < 15; s++) {
        uint32_t a0, a1, a2, a3;
        lds64(a0, a2, aA0 + (uint32_t)s * 32);
        lds64(a1, a3, aA1 + (uint32_t)s * 32);
        uint32_t af[4] = {tf32_bits(a0), tf32_bits(a1), tf32_bits(a2), tf32_bits(a3)};
#pragma unroll
        for (int nt = 0; nt < 24; nt++) {
            uint32_t b0, b1;
            lds64(b0, b1, aB + (uint32_t)(nt * 8 * PSTR) * 4 + (uint32_t)s * 32);
            mma_tf32(acc[nt], af, b0, b1);
        }
    }

    // ---- epilogue: fp16 stores ----
    const int t0 = row0 + m0 + g;
#pragma unroll
    for (int nt = 0; nt < 8; nt++) {  // K
        const int h = nt * 8 + 2 * tig;
        *(uint32_t*)&g_k[(long long)t0 * Hc + h] = pkh(acc[nt][1], acc[nt][0]);
        *(uint32_t*)&g_k[(long long)(t0 + 8) * Hc + h] = pkh(acc[nt][3], acc[nt][2]);
    }
#pragma unroll
    for (int nt = 8; nt < 16; nt++) {  // Q (scale folded)
        const int h = (nt - 8) * 8 + 2 * tig;
        *(uint32_t*)&g_q[(long long)t0 * Hc + h] =
            pkh(acc[nt][1] * SCALE, acc[nt][0] * SCALE);
        *(uint32_t*)&g_q[(long long)(t0 + 8) * Hc + h] =
            pkh(acc[nt][3] * SCALE, acc[nt][2] * SCALE);
    }
    {
        const int b = row0 >> 12, tl = t0 & 4095;
#pragma unroll
        for (int nt = 16; nt < 24; nt++) {  // V transposed [h][t]
            const int h = (nt - 16) * 8 + 2 * tig;
            __half* v0 = g_vt + ((long long)(b * Hc + h)) * Tc + tl;
            __half* v1 = g_vt + ((long long)(b * Hc + h + 1)) * Tc + tl;
            v0[0] = __float2half_rn(acc[nt][0]);
            v1[0] = __float2half_rn(acc[nt][1]);
            v0[8] = __float2half_rn(acc[nt][2]);
            v1[8] = __float2half_rn(acc[nt][3]);
        }
    }
}

// ---------------- Kernel 2: fp16 flash attention, 32 q/warp, key-split ----------------
// fp16 m16n8k16 (R5-verified fragment scheme: ldmatrix from [key][dim] K and
// [dim][key] V^T; C-frag -> P A-frag via pkh repack, no shuffles). 1-deep
// QK lookahead. cp.async traffic halved vs f32.
__global__ void __launch_bounds__(256, 1)
attn_kernel() {
    extern __shared__ char dsm[];  // 2 x STAGE

    const int tid = threadIdx.x;
    const int w = tid >> 5;
    const int lane = tid & 31;
    const int g = lane >> 2;
    const int tig = lane & 3;
    const int b = blockIdx.y;
    const int half_ = blockIdx.z;
    const int qbase = blockIdx.x * 256 + w * 32;
    const long long qrow = (long long)b * Tc + qbase + g;

    // ---- Q fragments (m16n8k16 A layout, R5-verified) ----
    uint32_t qf0[4][4], qf1[4][4];
#pragma unroll
    for (int s = 0; s < 4; s++) {
        const int d0 = 16 * s + 2 * tig;
        qf0[s][0] = *(const uint32_t*)&g_q[qrow * Hc + d0];
        qf0[s][1] = *(const uint32_t*)&g_q[(qrow + 8) * Hc + d0];
        qf0[s][2] = *(const uint32_t*)&g_q[qrow * Hc + d0 + 8];
        qf0[s][3] = *(const uint32_t*)&g_q[(qrow + 8) * Hc + d0 + 8];
        qf1[s][0] = *(const uint32_t*)&g_q[(qrow + 16) * Hc + d0];
        qf1[s][1] = *(const uint32_t*)&g_q[(qrow + 24) * Hc + d0];
        qf1[s][2] = *(const uint32_t*)&g_q[(qrow + 16) * Hc + d0 + 8];
        qf1[s][3] = *(const uint32_t*)&g_q[(qrow + 24) * Hc + d0 + 8];
    }

    float O0[8][4], O1[8][4];
#pragma unroll
    for (int j = 0; j < 8; j++)
#pragma unroll
        for (int i = 0; i < 4; i++) { O0[j][i] = 0.f; O1[j][i] = 0.f; }
    float rl0 = 0.f, rh0 = 0.f, rl1 = 0.f, rh1 = 0.f;

    const uint32_t sb = smem_u32(dsm);
    const uint32_t laneoff = (uint32_t)((lane & 7) * KSTR + ((lane >> 3) & 1) * 16);

    auto prefetch = [&](int kt, int p) {
        const uint32_t bb = sb + p * STAGE;
        const int ktg = half_ * HKT + kt;
        const long long kb = (long long)b * Tc + ktg * KTILE;
        const __half* vbase = g_vt + (long long)b * Hc * Tc + ktg * KTILE;
#pragma unroll
        for (int it = 0; it < 2; it++) {
            const int c = tid + it * 256;  // 0..511
            const int row = c >> 3, col = c & 7;
            const uint32_t doff = (uint32_t)(row * KSTR + col * 16);
            cpasync16(bb + doff, g_k + (kb + row) * Hc + col * 8);
            cpasync16(bb + VOFF + doff, vbase + (long long)row * Tc + col * 8);
        }
    };

    prefetch(0, 0);
    CP_COMMIT();

    float S[2][4][4];  // [parity][{n0q0,n0q1,n1q0,n1q1}][frag]

    for (int kt = 0; kt < HKT; kt++) {
        CP_WAIT0();
        __syncthreads();
        if (kt + 1 < HKT) {
            prefetch(kt + 1, (kt + 1) & 1);
            CP_COMMIT();
        }

        const uint32_t bb = sb + (kt & 1) * STAGE;
        const uint32_t aK = bb + laneoff;
        const uint32_t aV = bb + VOFF + laneoff;

        // QK for one 16-key chunk (2 n8-tiles x 4 k16-steps x 2 q-chunks)
        auto qk_chunk = [&](int jp, int p) {
            float* Sp = &S[p][0][0];
#pragma unroll
            for (int i = 0; i < 16; i++) Sp[i] = 0.f;
            const uint32_t base = aK + (uint32_t)jp * (16 * KSTR);
#pragma unroll
            for (int s = 0; s < 4; s++) {
                uint32_t b0, b1, c0, c1;
                ldsm2(b0, b1, base + s * 32);              // keys 16jp..+7
                mma_f16(S[p][0], qf0[s], b0, b1);
                mma_f16(S[p][1], qf1[s], b0, b1);
                ldsm2(c0, c1, base + 8 * KSTR + s * 32);   // keys 16jp+8..+15
                mma_f16(S[p][2], qf0[s], c0, c1);
                mma_f16(S[p][3], qf1[s], c0, c1);
            }
        };

        qk_chunk(0, 0);

#pragma unroll
        for (int jp = 0; jp < 4; jp++) {
            if (jp < 3) qk_chunk(jp + 1, (jp + 1) & 1);

            const float (*Sc)[4] = S[jp & 1];
            // exp all 16 logits
            const float e0 = __expf(Sc[0][0]), e1 = __expf(Sc[0][1]);
            const float e2 = __expf(Sc[0][2]), e3 = __expf(Sc[0][3]);
            const float g0 = __expf(Sc[1][0]), g1 = __expf(Sc[1][1]);
            const float g2 = __expf(Sc[1][2]), g3 = __expf(Sc[1][3]);
            const float h0 = __expf(Sc[2][0]), h1 = __expf(Sc[2][1]);
            const float h2 = __expf(Sc[2][2]), h3 = __expf(Sc[2][3]);
            const float i0 = __expf(Sc[3][0]), i1 = __expf(Sc[3][1]);
            const float i2 = __expf(Sc[3][2]), i3 = __expf(Sc[3][3]);
            rl0 += (e0 + e1) + (h0 + h1);
            rh0 += (e2 + e3) + (h2 + h3);
            rl1 += (g0 + g1) + (i0 + i1);
            rh1 += (g2 + g3) + (i2 + i3);

            uint32_t pf0[4], pf1[4];
            pf0[0] = pkh(e1, e0);
            pf0[1] = pkh(e3, e2);
            pf0[2] = pkh(h1, h0);
            pf0[3] = pkh(h3, h2);
            pf1[0] = pkh(g1, g0);
            pf1[1] = pkh(g3, g2);
            pf1[2] = pkh(i1, i0);
            pf1[3] = pkh(i3, i2);

            // PV: V^T B-frags shared by both q-chunks
            const uint32_t vb = aV + (uint32_t)jp * 32;
#pragma unroll
            for (int jd = 0; jd < 8; jd++) {
                uint32_t b0, b1;
                ldsm2(b0, b1, vb + (uint32_t)jd * (8 * KSTR));
                mma_f16(O0[jd], pf0, b0, b1);
                mma_f16(O1[jd], pf1, b0, b1);
            }
        }
    }

    // ---- reduce rowsums over tig; write partial O + rowsums ----
    rl0 += __shfl_xor_sync(0xffffffffu, rl0, 1);
    rl0 += __shfl_xor_sync(0xffffffffu, rl0, 2);
    rh0 += __shfl_xor_sync(0xffffffffu, rh0, 1);
    rh0 += __shfl_xor_sync(0xffffffffu, rh0, 2);
    rl1 += __shfl_xor_sync(0xffffffffu, rl1, 1);
    rl1 += __shfl_xor_sync(0xffffffffu, rl1, 2);
    rh1 += __shfl_xor_sync(0xffffffffu, rh1, 1);
    rh1 += __shfl_xor_sync(0xffffffffu, rh1, 2);

    float* acc = g_acc[half_];
    if (tig == 0) {
        float* rs = g_rs[half_] + (long long)b * Tc + qbase + g;
        rs[0] = rl0;
        rs[8] = rh0;
        rs[16] = rl1;
        rs[24] = rh1;
    }
#pragma unroll
    for (int j = 0; j < 8; j++) {
        const int d0 = 8 * j + 2 * tig;
        *(float2*)&acc[qrow * Hc + d0] = make_float2(O0[j][0], O0[j][1]);
        *(float2*)&acc[(qrow + 8) * Hc + d0] = make_float2(O0[j][2], O0[j][3]);
        *(float2*)&acc[(qrow + 16) * Hc + d0] = make_float2(O1[j][0], O1[j][1]);
        *(float2*)&acc[(qrow + 24) * Hc + d0] = make_float2(O1[j][2], O1[j][3]);
    }
}

// ---------------- Kernel 3: combine key-halves + normalize ----------------
__global__ void __launch_bounds__(256)
combine_kernel(float* __restrict__ out) {
    const int idx = blockIdx.x * 256 + threadIdx.x;  // 0 .. B*T*16-1
    const int row = idx >> 4;
    const float4 a = reinterpret_cast<const float4*>(g_acc[0])[idx];
    const float4 d = reinterpret_cast<const float4*>(g_acc[1])[idx];
    const float inv = 1.0f / (g_rs[0][row] + g_rs[1][row]);
    float4 o;
    o.x = (a.x + d.x) * inv;
    o.y = (a.y + d.y) * inv;
    o.z = (a.z + d.z) * inv;
    o.w = (a.w + d.w) * inv;
    reinterpret_cast<float4*>(out)[idx] = o;
}

extern "C" void kernel_launch(void* const* d_in, const int* in_sizes, int n_in,
                              void* d_out, int out_size) {
    // x is the unique large tensor; weights keep relative order Wk, Wq, Wv.
    const float* x = nullptr;
    const float* w[3] = {nullptr, nullptr, nullptr};
    int wn = 0;
    for (int i = 0; i < n_in; i++) {
        if (in_sizes[i] == Bc * Tc * Cc) x = (const float*)d_in[i];
        else if (wn < 3) w[wn++] = (const float*)d_in[i];
    }

    static bool configured = false;
    if (!configured) {
        cudaFuncSetAttribute(proj_kernel, cudaFuncAttributeMaxDynamicSharedMemorySize,
                             PROJ_SMEM);
        cudaFuncSetAttribute(attn_kernel, cudaFuncAttributeMaxDynamicSharedMemorySize,
                             2 * STAGE);
        configured = true;
    }

    proj_kernel<<<128, 256, PROJ_SMEM>>>(x, w[0], w[1], w[2]);

    dim3 grid(Tc / 256, Bc, 2);
    attn_kernel<<<grid, 256, 2 * STAGE>>>();

    combine_kernel<<<Bc * Tc * 16 / 256, 256>>>((float*)d_out);
}

// round 17
// speedup vs baseline: 1.6359x; 1.0036x over previous
#include <cuda_runtime.h>
#include <cuda_fp16.h>
#include <cstdint>

// ---------------- problem constants ----------------
constexpr int Bc = 4, Tc = 4096, Cc = 120, Hc = 64;
constexpr float SCALE = 0.09128709291752768f;  // 1/sqrt(C)
constexpr int KTILE = 64;
constexpr int HKT = 32;            // key tiles per half (Tc/KTILE/2)
constexpr int KSTR = 144;          // smem row stride bytes (72 halves)
constexpr int VOFF = 64 * KSTR;    // V region offset in stage
constexpr int STAGE = 2 * 64 * KSTR;  // 18432 bytes per stage (K + V)

// ---------------- device scratch (allocation-free rule) ----------------
__device__ __align__(16) __half g_q[Bc * Tc * Hc];   // fp16, SCALE folded
__device__ __align__(16) __half g_k[Bc * Tc * Hc];   // fp16
__device__ __align__(16) __half g_vt[Bc * Hc * Tc];  // fp16, [b][h][t]
__device__ __align__(16) float g_acc[2][Bc * Tc * Hc];  // partial O per key-half
__device__ __align__(16) float g_rs[2][Bc * Tc];        // partial rowsums

// ---------------- PTX helpers (sm_80+ baseline) ----------------
__device__ __forceinline__ void mma_f16(float* d, const uint32_t* a,
                                        uint32_t b0, uint32_t b1) {
    asm volatile(
        "mma.sync.aligned.m16n8k16.row.col.f32.f16.f16.f32 "
        "{%0,%1,%2,%3}, {%4,%5,%6,%7}, {%8,%9}, {%0,%1,%2,%3};"
        : "+f"(d[0]), "+f"(d[1]), "+f"(d[2]), "+f"(d[3])
        : "r"(a[0]), "r"(a[1]), "r"(a[2]), "r"(a[3]), "r"(b0), "r"(b1));
}
__device__ __forceinline__ void mma_tf32(float* d, const uint32_t* a,
                                         uint32_t b0, uint32_t b1) {
    asm volatile(
        "mma.sync.aligned.m16n8k8.row.col.f32.tf32.tf32.f32 "
        "{%0,%1,%2,%3}, {%4,%5,%6,%7}, {%8,%9}, {%0,%1,%2,%3};"
        : "+f"(d[0]), "+f"(d[1]), "+f"(d[2]), "+f"(d[3])
        : "r"(a[0]), "r"(a[1]), "r"(a[2]), "r"(a[3]), "r"(b0), "r"(b1));
}
__device__ __forceinline__ void ldsm2(uint32_t& r0, uint32_t& r1, uint32_t addr) {
    asm volatile("ldmatrix.sync.aligned.m8n8.x2.shared.b16 {%0,%1}, [%2];"
                 : "=r"(r0), "=r"(r1) : "r"(addr));
}
__device__ __forceinline__ void lds64(uint32_t& r0, uint32_t& r1, uint32_t a) {
    asm volatile("ld.shared.v2.b32 {%0,%1}, [%2];" : "=r"(r0), "=r"(r1) : "r"(a));
}
__device__ __forceinline__ uint32_t smem_u32(const void* p) {
    uint32_t a;
    asm("{ .reg .u64 t; cvta.to.shared.u64 t, %1; cvt.u32.u64 %0, t; }"
        : "=r"(a) : "l"(p));
    return a;
}
__device__ __forceinline__ void cpasync16(uint32_t dst, const void* src) {
    asm volatile("cp.async.ca.shared.global [%0], [%1], 16;" :: "r"(dst), "l"(src));
}
#define CP_COMMIT() asm volatile("cp.async.commit_group;" ::: "memory")
#define CP_WAIT0()  asm volatile("cp.async.wait_group 0;" ::: "memory")

__device__ __forceinline__ float to_tf32(float x) {
    float r;
    asm("cvt.rna.tf32.f32 %0, %1;" : "=f"(r) : "f"(x));
    return r;
}
__device__ __forceinline__ uint32_t tf32_bits(uint32_t u) {
    float r;
    asm("cvt.rna.tf32.f32 %0, %1;" : "=f"(r) : "f"(__uint_as_float(u)));
    return __float_as_uint(r);
}
__device__ __forceinline__ uint32_t pkh(float hi, float lo) {
    uint32_t r;
    asm("cvt.rn.f16x2.f32 %0, %1, %2;" : "=r"(r) : "f"(hi), "f"(lo));
    return r;
}

// ---------------- Kernel 1: tf32 MMA QKV projection (matrix-split) ----------------
// grid (128 row-chunks, 3 matrices) x 256 thr. Per CTA: one W (35 KB) + x tile
// (70 KB) -> 104 KB smem -> 2 CTAs/SM: neighbor prologue hides latency.
constexpr int PSTR = 136;  // smem row stride in words (136 % 32 == 8)
constexpr int PROJ_SMEM = (64 * PSTR + 128 * PSTR) * 4;  // 104,448 B
__global__ void __launch_bounds__(256, 2)
proj_kernel(const float* __restrict__ x,
            const float* __restrict__ Wk,
            const float* __restrict__ Wq,
            const float* __restrict__ Wv) {
    extern __shared__ float ps[];
    float* sW = ps;                // [64][PSTR]   this matrix's W^T
    float* sx = ps + 64 * PSTR;    // [128][PSTR]  raw fp32 x

    const int tid = threadIdx.x;
    const int m = blockIdx.y;
    const int row0 = blockIdx.x * 128;
    const float* W = (m == 0) ? Wk : (m == 1) ? Wq : Wv;

    // ---- x tile via cp.async FIRST (raw) ----
    {
        const uint32_t sxa = smem_u32(sx);
        const float4* xg = reinterpret_cast<const float4*>(x + (long long)row0 * Cc);
#pragma unroll
        for (int it = 0; it < 15; it++) {
            const int i = tid + it * 256;
            const int r = i / 30, c4 = i % 30;
            cpasync16(sxa + (uint32_t)((r * PSTR + c4 * 4) * 4), xg + i);
        }
        CP_COMMIT();
    }
    // ---- W transposed into smem (tf32-rounded) while x is in flight ----
#pragma unroll
    for (int it = 0; it < 30; it++) {
        const int i = tid + it * 256;  // i < 7680
        const int c = i >> 6, h = i & 63;
        sW[h * PSTR + c] = to_tf32(W[i]);
    }
    CP_WAIT0();
    __syncthreads();

    const int w = tid >> 5, lane = tid & 31;
    const int g = lane >> 2, tig = lane & 3;
    const int m0 = w * 16;

    float acc[8][4];
#pragma unroll
    for (int nt = 0; nt < 8; nt++)
#pragma unroll
        for (int i = 0; i < 4; i++) acc[nt][i] = 0.f;

    const uint32_t aA0 = smem_u32(sx) + (uint32_t)(((m0 + g) * PSTR + 2 * tig) * 4);
    const uint32_t aA1 = aA0 + (uint32_t)(8 * PSTR * 4);
    const uint32_t aB  = smem_u32(sW) + (uint32_t)((g * PSTR + 2 * tig) * 4);

#pragma unroll
    for (int s = 0; s < 15; s++) {
        uint32_t a0, a1, a2, a3;
        lds64(a0, a2, aA0 + (uint32_t)s * 32);
        lds64(a1, a3, aA1 + (uint32_t)s * 32);
        uint32_t af[4] = {tf32_bits(a0), tf32_bits(a1), tf32_bits(a2), tf32_bits(a3)};
#pragma unroll
        for (int nt = 0; nt < 8; nt++) {
            uint32_t b0, b1;
            lds64(b0, b1, aB + (uint32_t)(nt * 8 * PSTR) * 4 + (uint32_t)s * 32);
            mma_tf32(acc[nt], af, b0, b1);
        }
    }

    // ---- epilogue (uniform per CTA) ----
    const int t0 = row0 + m0 + g;
    if (m == 0) {  // K
#pragma unroll
        for (int nt = 0; nt < 8; nt++) {
            const int h = nt * 8 + 2 * tig;
            *(uint32_t*)&g_k[(long long)t0 * Hc + h] = pkh(acc[nt][1], acc[nt][0]);
            *(uint32_t*)&g_k[(long long)(t0 + 8) * Hc + h] = pkh(acc[nt][3], acc[nt][2]);
        }
    } else if (m == 1) {  // Q (scale folded)
#pragma unroll
        for (int nt = 0; nt < 8; nt++) {
            const int h = nt * 8 + 2 * tig;
            *(uint32_t*)&g_q[(long long)t0 * Hc + h] =
                pkh(acc[nt][1] * SCALE, acc[nt][0] * SCALE);
            *(uint32_t*)&g_q[(long long)(t0 + 8) * Hc + h] =
                pkh(acc[nt][3] * SCALE, acc[nt][2] * SCALE);
        }
    } else {  // V transposed [h][t]
        const int b = row0 >> 12, tl = t0 & 4095;
#pragma unroll
        for (int nt = 0; nt < 8; nt++) {
            const int h = nt * 8 + 2 * tig;
            __half* v0 = g_vt + ((long long)(b * Hc + h)) * Tc + tl;
            __half* v1 = g_vt + ((long long)(b * Hc + h + 1)) * Tc + tl;
            v0[0] = __float2half_rn(acc[nt][0]);
            v1[0] = __float2half_rn(acc[nt][1]);
            v0[8] = __float2half_rn(acc[nt][2]);
            v1[8] = __float2half_rn(acc[nt][3]);
        }
    }
}

// ---------------- Kernel 2: fp16 flash attention, 32 q/warp, key-split ----------------
__global__ void __launch_bounds__(256, 1)
attn_kernel() {
    extern __shared__ char dsm[];  // 2 x STAGE

    const int tid = threadIdx.x;
    const int w = tid >> 5;
    const int lane = tid & 31;
    const int g = lane >> 2;
    const int tig = lane & 3;
    const int b = blockIdx.y;
    const int half_ = blockIdx.z;
    const int qbase = blockIdx.x * 256 + w * 32;
    const long long qrow = (long long)b * Tc + qbase + g;

    // ---- Q fragments (m16n8k16 A layout) ----
    uint32_t qf0[4][4], qf1[4][4];
#pragma unroll
    for (int s = 0; s < 4; s++) {
        const int d0 = 16 * s + 2 * tig;
        qf0[s][0] = *(const uint32_t*)&g_q[qrow * Hc + d0];
        qf0[s][1] = *(const uint32_t*)&g_q[(qrow + 8) * Hc + d0];
        qf0[s][2] = *(const uint32_t*)&g_q[qrow * Hc + d0 + 8];
        qf0[s][3] = *(const uint32_t*)&g_q[(qrow + 8) * Hc + d0 + 8];
        qf1[s][0] = *(const uint32_t*)&g_q[(qrow + 16) * Hc + d0];
        qf1[s][1] = *(const uint32_t*)&g_q[(qrow + 24) * Hc + d0];
        qf1[s][2] = *(const uint32_t*)&g_q[(qrow + 16) * Hc + d0 + 8];
        qf1[s][3] = *(const uint32_t*)&g_q[(qrow + 24) * Hc + d0 + 8];
    }

    float O0[8][4], O1[8][4];
#pragma unroll
    for (int j = 0; j < 8; j++)
#pragma unroll
        for (int i = 0; i < 4; i++) { O0[j][i] = 0.f; O1[j][i] = 0.f; }
    float rl0 = 0.f, rh0 = 0.f, rl1 = 0.f, rh1 = 0.f;

    const uint32_t sb = smem_u32(dsm);
    const uint32_t laneoff = (uint32_t)((lane & 7) * KSTR + ((lane >> 3) & 1) * 16);

    auto prefetch = [&](int kt, int p) {
        const uint32_t bb = sb + p * STAGE;
        const int ktg = half_ * HKT + kt;
        const long long kb = (long long)b * Tc + ktg * KTILE;
        const __half* vbase = g_vt + (long long)b * Hc * Tc + ktg * KTILE;
#pragma unroll
        for (int it = 0; it < 2; it++) {
            const int c = tid + it * 256;  // 0..511
            const int row = c >> 3, col = c & 7;
            const uint32_t doff = (uint32_t)(row * KSTR + col * 16);
            cpasync16(bb + doff, g_k + (kb + row) * Hc + col * 8);
            cpasync16(bb + VOFF + doff, vbase + (long long)row * Tc + col * 8);
        }
    };

    prefetch(0, 0);
    CP_COMMIT();

    float S[2][4][4];  // [parity][{n0q0,n0q1,n1q0,n1q1}][frag]

    for (int kt = 0; kt < HKT; kt++) {
        CP_WAIT0();
        __syncthreads();
        if (kt + 1 < HKT) {
            prefetch(kt + 1, (kt + 1) & 1);
            CP_COMMIT();
        }

        const uint32_t bb = sb + (kt & 1) * STAGE;
        const uint32_t aK = bb + laneoff;
        const uint32_t aV = bb + VOFF + laneoff;

        auto qk_chunk = [&](int jp, int p) {
            float* Sp = &S[p][0][0];
#pragma unroll
            for (int i = 0; i < 16; i++) Sp[i] = 0.f;
            const uint32_t base = aK + (uint32_t)jp * (16 * KSTR);
#pragma unroll
            for (int s = 0; s < 4; s++) {
                uint32_t b0, b1, c0, c1;
                ldsm2(b0, b1, base + s * 32);
                mma_f16(S[p][0], qf0[s], b0, b1);
                mma_f16(S[p][1], qf1[s], b0, b1);
                ldsm2(c0, c1, base + 8 * KSTR + s * 32);
                mma_f16(S[p][2], qf0[s], c0, c1);
                mma_f16(S[p][3], qf1[s], c0, c1);
            }
        };

        qk_chunk(0, 0);

#pragma unroll
        for (int jp = 0; jp < 4; jp++) {
            if (jp < 3) qk_chunk(jp + 1, (jp + 1) & 1);

            const float (*Sc)[4] = S[jp & 1];
            const float e0 = __expf(Sc[0][0]), e1 = __expf(Sc[0][1]);
            const float e2 = __expf(Sc[0][2]), e3 = __expf(Sc[0][3]);
            const float g0 = __expf(Sc[1][0]), g1 = __expf(Sc[1][1]);
            const float g2 = __expf(Sc[1][2]), g3 = __expf(Sc[1][3]);
            const float h0 = __expf(Sc[2][0]), h1 = __expf(Sc[2][1]);
            const float h2 = __expf(Sc[2][2]), h3 = __expf(Sc[2][3]);
            const float i0 = __expf(Sc[3][0]), i1 = __expf(Sc[3][1]);
            const float i2 = __expf(Sc[3][2]), i3 = __expf(Sc[3][3]);
            rl0 += (e0 + e1) + (h0 + h1);
            rh0 += (e2 + e3) + (h2 + h3);
            rl1 += (g0 + g1) + (i0 + i1);
            rh1 += (g2 + g3) + (i2 + i3);

            uint32_t pf0[4], pf1[4];
            pf0[0] = pkh(e1, e0);
            pf0[1] = pkh(e3, e2);
            pf0[2] = pkh(h1, h0);
            pf0[3] = pkh(h3, h2);
            pf1[0] = pkh(g1, g0);
            pf1[1] = pkh(g3, g2);
            pf1[2] = pkh(i1, i0);
            pf1[3] = pkh(i3, i2);

            const uint32_t vb = aV + (uint32_t)jp * 32;
#pragma unroll
            for (int jd = 0; jd < 8; jd++) {
                uint32_t b0, b1;
                ldsm2(b0, b1, vb + (uint32_t)jd * (8 * KSTR));
                mma_f16(O0[jd], pf0, b0, b1);
                mma_f16(O1[jd], pf1, b0, b1);
            }
        }
    }

    // ---- reduce rowsums over tig; write partial O + rowsums ----
    rl0 += __shfl_xor_sync(0xffffffffu, rl0, 1);
    rl0 += __shfl_xor_sync(0xffffffffu, rl0, 2);
    rh0 += __shfl_xor_sync(0xffffffffu, rh0, 1);
    rh0 += __shfl_xor_sync(0xffffffffu, rh0, 2);
    rl1 += __shfl_xor_sync(0xffffffffu, rl1, 1);
    rl1 += __shfl_xor_sync(0xffffffffu, rl1, 2);
    rh1 += __shfl_xor_sync(0xffffffffu, rh1, 1);
    rh1 += __shfl_xor_sync(0xffffffffu, rh1, 2);

    float* acc = g_acc[half_];
    if (tig == 0) {
        float* rs = g_rs[half_] + (long long)b * Tc + qbase + g;
        rs[0] = rl0;
        rs[8] = rh0;
        rs[16] = rl1;
        rs[24] = rh1;
    }
#pragma unroll
    for (int j = 0; j < 8; j++) {
        const int d0 = 8 * j + 2 * tig;
        *(float2*)&acc[qrow * Hc + d0] = make_float2(O0[j][0], O0[j][1]);
        *(float2*)&acc[(qrow + 8) * Hc + d0] = make_float2(O0[j][2], O0[j][3]);
        *(float2*)&acc[(qrow + 16) * Hc + d0] = make_float2(O1[j][0], O1[j][1]);
        *(float2*)&acc[(qrow + 24) * Hc + d0] = make_float2(O1[j][2], O1[j][3]);
    }
}

// ---------------- Kernel 3: combine key-halves + normalize ----------------
__global__ void __launch_bounds__(256)
combine_kernel(float* __restrict__ out) {
    const int idx = blockIdx.x * 256 + threadIdx.x;  // 0 .. B*T*16-1
    const int row = idx >> 4;
    const float4 a = reinterpret_cast<const float4*>(g_acc[0])[idx];
    const float4 d = reinterpret_cast<const float4*>(g_acc[1])[idx];
    const float inv = 1.0f / (g_rs[0][row] + g_rs[1][row]);
    float4 o;
    o.x = (a.x + d.x) * inv;
    o.y = (a.y + d.y) * inv;
    o.z = (a.z + d.z) * inv;
    o.w = (a.w + d.w) * inv;
    reinterpret_cast<float4*>(out)[idx] = o;
}

extern "C" void kernel_launch(void* const* d_in, const int* in_sizes, int n_in,
                              void* d_out, int out_size) {
    // x is the unique large tensor; weights keep relative order Wk, Wq, Wv.
    const float* x = nullptr;
    const float* w[3] = {nullptr, nullptr, nullptr};
    int wn = 0;
    for (int i = 0; i < n_in; i++) {
        if (in_sizes[i] == Bc * Tc * Cc) x = (const float*)d_in[i];
        else if (wn < 3) w[wn++] = (const float*)d_in[i];
    }

    static bool configured = false;
    if (!configured) {
        cudaFuncSetAttribute(proj_kernel, cudaFuncAttributeMaxDynamicSharedMemorySize,
                             PROJ_SMEM);
        cudaFuncSetAttribute(attn_kernel, cudaFuncAttributeMaxDynamicSharedMemorySize,
                             2 * STAGE);
        configured = true;
    }

    dim3 pgrid(128, 3);
    proj_kernel<<<pgrid, 256, PROJ_SMEM>>>(x, w[0], w[1], w[2]);

    dim3 grid(Tc / 256, Bc, 2);
    attn_kernel<<<grid, 256, 2 * STAGE>>>();

    combine_kernel<<<Bc * Tc * 16 / 256, 256>>>((float*)d_out);
}